// round 2
// baseline (speedup 1.0000x reference)
#include <cuda_runtime.h>
#include <cuda_bf16.h>
#include <math.h>

// ---------------------------------------------------------------------------
// Problem constants (match reference_code)
// ---------------------------------------------------------------------------
#define NUM_E   8
#define TOPK    2
#define T_TOK   8192            // BS*SL = 4*2048
#define NK      (T_TOK * TOPK)  // 16384 flattened routing entries
#define HS      1024
#define FFN     4096
#define CAP     2048            // int(1.0 * TOPK * T_TOK / NUM_E)

// ---------------------------------------------------------------------------
// Scratch (device globals: the sanctioned no-allocation workaround)
// ---------------------------------------------------------------------------
__device__ int   g_flat_slot[NK];                              // entry -> e*CAP+p, -1 dropped
__device__ int   g_slot_token[NUM_E * CAP];                    // slot -> token, -1 unfilled
__device__ float g_h[(size_t)NUM_E * CAP * FFN];               // 256 MB activations
__device__ float g_out[(size_t)NUM_E * CAP * HS];              // 64 MB expert outputs

// ---------------------------------------------------------------------------
// Kernel 1: routing. Stable per-expert positions (== stable argsort semantics).
// Single block, 512 threads, 32 entries each.
// ---------------------------------------------------------------------------
__global__ void routing_kernel(const int* __restrict__ te)
{
    __shared__ int shist[512][NUM_E];   // per-thread histograms -> exclusive prefix
    const int tid   = threadIdx.x;
    const int PER   = NK / 512;         // 32
    const int start = tid * PER;

    // init gather map to "unfilled" (NUM_E*CAP == NK == 16384, same coverage)
    #pragma unroll
    for (int i = 0; i < PER; i++) g_slot_token[start + i] = -1;

    // pass 1: local histogram
    int h[NUM_E];
    #pragma unroll
    for (int e = 0; e < NUM_E; e++) h[e] = 0;
    #pragma unroll 1
    for (int i = 0; i < PER; i++) {
        int ex = te[start + i];
        h[ex]++;
    }
    #pragma unroll
    for (int e = 0; e < NUM_E; e++) shist[tid][e] = h[e];
    __syncthreads();

    // exclusive scan across threads, one expert per scanning thread
    if (tid < NUM_E) {
        int acc = 0;
        #pragma unroll 1
        for (int t = 0; t < 512; t++) {
            int v = shist[t][tid];
            shist[t][tid] = acc;
            acc += v;
        }
    }
    __syncthreads();

    // pass 2: assign stable positions, emit gather + scatter maps
    int run[NUM_E];
    #pragma unroll
    for (int e = 0; e < NUM_E; e++) run[e] = shist[tid][e];
    #pragma unroll 1
    for (int i = 0; i < PER; i++) {
        int idx = start + i;
        int ex  = te[idx];
        int pos = run[ex]++;
        if (pos < CAP) {
            int slot = ex * CAP + pos;
            g_flat_slot[idx]   = slot;
            g_slot_token[slot] = idx >> 1;   // token index = flattened / TOPK
        } else {
            g_flat_slot[idx] = -1;           // dropped
        }
    }
}

// ---------------------------------------------------------------------------
// GeLU (tanh approximation — matches jax.nn.gelu default approximate=True)
// ---------------------------------------------------------------------------
__device__ __forceinline__ float gelu_tanh(float x)
{
    float x3 = x * x * x;
    return 0.5f * x * (1.0f + tanhf(0.7978845608028654f * (x + 0.044715f * x3)));
}

// ---------------------------------------------------------------------------
// Kernel 2/3: tiled fp32 GEMM, 128x128x16, 256 threads, 8x8 microtile.
//   INDIRECT: A rows gathered via g_slot_token (token rows of x), C = g_h, +GeLU
//   !INDIRECT: A = g_h (dense per expert), C = g_out, no activation
// B is per-expert [K, N] row-major at Bbase + e*K*N.
// ---------------------------------------------------------------------------
template <bool GELU, bool INDIRECT>
__global__ __launch_bounds__(256)
void gemm128(const float* __restrict__ Aparam,
             const float* __restrict__ Bbase,
             int M, int N, int K)
{
    const int BM = 128, BN = 128, BK = 16;
    const int e  = blockIdx.z;
    const int m0 = blockIdx.y * BM;
    const int n0 = blockIdx.x * BN;

    const float* Bp = Bbase + (size_t)e * K * N;
    const float* Ap;
    float*       Cp;
    if (INDIRECT) {
        Ap = Aparam;                                   // flat x [T_TOK, HS]
        Cp = g_h + (size_t)e * M * N;
    } else {
        Ap = g_h + (size_t)e * M * K;
        Cp = g_out + (size_t)e * M * N;
    }

    __shared__ float As[BK][BM];
    __shared__ float Bs[BK][BN];
    __shared__ int   srow[BM];

    const int tid = threadIdx.x;
    if (INDIRECT && tid < BM)
        srow[tid] = g_slot_token[e * CAP + m0 + tid];
    __syncthreads();

    float acc[8][8];
    #pragma unroll
    for (int i = 0; i < 8; i++)
        #pragma unroll
        for (int j = 0; j < 8; j++) acc[i][j] = 0.0f;

    const int tx = tid & 15;   // 0..15 -> cols tx*4 and 64+tx*4
    const int ty = tid >> 4;   // 0..15 -> rows ty*4 and 64+ty*4

    for (int k0 = 0; k0 < K; k0 += BK) {
        // --- load A tile (128 rows x 16 k), 512 float4, 2 per thread ---
        #pragma unroll
        for (int l = 0; l < 2; l++) {
            int v   = tid * 2 + l;
            int row = v >> 2;          // 4 float4 per row
            int kc  = (v & 3) * 4;
            float4 val;
            if (INDIRECT) {
                int tok = srow[row];
                if (tok >= 0)
                    val = *(const float4*)&Aparam[(size_t)tok * K + k0 + kc];
                else
                    val = make_float4(0.f, 0.f, 0.f, 0.f);
            } else {
                val = *(const float4*)&Ap[(size_t)(m0 + row) * K + k0 + kc];
            }
            As[kc + 0][row] = val.x;
            As[kc + 1][row] = val.y;
            As[kc + 2][row] = val.z;
            As[kc + 3][row] = val.w;
        }
        // --- load B tile (16 k-rows x 128 cols), 512 float4, 2 per thread ---
        #pragma unroll
        for (int l = 0; l < 2; l++) {
            int v  = tid + l * 256;
            int kr = v >> 5;           // 32 float4 per k-row
            int nc = (v & 31) * 4;
            float4 val = *(const float4*)&Bp[(size_t)(k0 + kr) * N + n0 + nc];
            *(float4*)&Bs[kr][nc] = val;
        }
        __syncthreads();

        #pragma unroll
        for (int k = 0; k < BK; k++) {
            float4 a0 = *(const float4*)&As[k][ty * 4];
            float4 a1 = *(const float4*)&As[k][64 + ty * 4];
            float4 b0 = *(const float4*)&Bs[k][tx * 4];
            float4 b1 = *(const float4*)&Bs[k][64 + tx * 4];
            float a[8] = {a0.x, a0.y, a0.z, a0.w, a1.x, a1.y, a1.z, a1.w};
            float b[8] = {b0.x, b0.y, b0.z, b0.w, b1.x, b1.y, b1.z, b1.w};
            #pragma unroll
            for (int i = 0; i < 8; i++)
                #pragma unroll
                for (int j = 0; j < 8; j++)
                    acc[i][j] += a[i] * b[j];
        }
        __syncthreads();
    }

    // --- epilogue ---
    #pragma unroll
    for (int ih = 0; ih < 2; ih++) {
        #pragma unroll
        for (int i = 0; i < 4; i++) {
            int row = m0 + ih * 64 + ty * 4 + i;
            #pragma unroll
            for (int jh = 0; jh < 2; jh++) {
                float* a = &acc[ih * 4 + i][jh * 4];
                float4 o;
                if (GELU) {
                    o.x = gelu_tanh(a[0]); o.y = gelu_tanh(a[1]);
                    o.z = gelu_tanh(a[2]); o.w = gelu_tanh(a[3]);
                } else {
                    o.x = a[0]; o.y = a[1]; o.z = a[2]; o.w = a[3];
                }
                int col = n0 + jh * 64 + tx * 4;
                *(float4*)&Cp[(size_t)row * N + col] = o;
            }
        }
    }
}

// ---------------------------------------------------------------------------
// Kernel 4: combine. Each token fully owns its output row -> no atomics,
// full overwrite of d_out (which is poisoned, not zeroed).
// ---------------------------------------------------------------------------
__global__ void combine_kernel(const float* __restrict__ ew,
                               const float* __restrict__ bias,
                               float* __restrict__ y)
{
    const int t = blockIdx.x;            // token
    const int c = threadIdx.x * 4;       // 256 threads x float4 = 1024 cols

    float4 acc = *(const float4*)&bias[c];
    #pragma unroll
    for (int k = 0; k < TOPK; k++) {
        int slot = g_flat_slot[t * TOPK + k];
        if (slot >= 0) {
            float  w = ew[t * TOPK + k];
            float4 v = *(const float4*)&g_out[(size_t)slot * HS + c];
            acc.x += v.x * w; acc.y += v.y * w;
            acc.z += v.z * w; acc.w += v.w * w;
        }
    }
    *(float4*)&y[(size_t)t * HS + c] = acc;
}

// ---------------------------------------------------------------------------
// Entry point
// ---------------------------------------------------------------------------
extern "C" void kernel_launch(void* const* d_in, const int* in_sizes, int n_in,
                              void* d_out, int out_size)
{
    const float* x    = (const float*)d_in[0];   // [8192, 1024]
    const float* ew   = (const float*)d_in[1];   // [16384]
    const float* w1   = (const float*)d_in[2];   // [8, 1024, 4096]
    const float* w2   = (const float*)d_in[3];   // [8, 4096, 1024]
    const float* bias = (const float*)d_in[4];   // [1024]
    const int*   te   = (const int*)d_in[5];     // [16384]
    float*       y    = (float*)d_out;           // [8192, 1024]

    // 1) routing
    routing_kernel<<<1, 512>>>(te);

    // 2) GEMM1 + GeLU: x[gathered] @ w1 -> g_h   (M=2048, N=4096, K=1024)
    {
        dim3 grid(FFN / 128, CAP / 128, NUM_E);
        gemm128<true, true><<<grid, 256>>>(x, w1, CAP, FFN, HS);
    }

    // 3) GEMM2: g_h @ w2 -> g_out               (M=2048, N=1024, K=4096)
    {
        dim3 grid(HS / 128, CAP / 128, NUM_E);
        gemm128<false, false><<<grid, 256>>>(nullptr, w2, CAP, FFN /*K*/ == FFN ? HS : HS, FFN);
    }

    // 4) combine -> y
    combine_kernel<<<T_TOK, 256>>>(ew, bias, y);
}

// round 6
// speedup vs baseline: 2.0704x; 2.0704x over previous
#include <cuda_runtime.h>
#include <cuda_bf16.h>
#include <math.h>
#include <stdint.h>

// ---------------------------------------------------------------------------
// Problem constants
// ---------------------------------------------------------------------------
#define NUM_E   8
#define TOPK    2
#define T_TOK   8192
#define NK      (T_TOK * TOPK)
#define HS      1024
#define FFN     4096
#define CAP     2048

// ---------------------------------------------------------------------------
// Device scratch
// ---------------------------------------------------------------------------
__device__ int            g_flat_slot[NK];
__device__ int            g_slot_token[NUM_E * CAP];
__device__ __nv_bfloat16  g_xg_hi[(size_t)NUM_E * CAP * HS];
__device__ __nv_bfloat16  g_xg_lo[(size_t)NUM_E * CAP * HS];
__device__ __nv_bfloat16  g_w1t_hi[(size_t)NUM_E * FFN * HS];   // [E][FFN][HS]
__device__ __nv_bfloat16  g_w1t_lo[(size_t)NUM_E * FFN * HS];
__device__ __nv_bfloat16  g_w2t_hi[(size_t)NUM_E * HS * FFN];   // [E][HS][FFN]
__device__ __nv_bfloat16  g_w2t_lo[(size_t)NUM_E * HS * FFN];
__device__ __nv_bfloat16  g_h_hi[(size_t)NUM_E * CAP * FFN];
__device__ __nv_bfloat16  g_h_lo[(size_t)NUM_E * CAP * FFN];
__device__ float          g_out[(size_t)NUM_E * CAP * HS];

// ---------------------------------------------------------------------------
// PTX helpers (all baseline PTX, valid at compute_103 target)
// ---------------------------------------------------------------------------
__device__ __forceinline__ uint32_t smem_u32(const void* p) {
    uint32_t a;
    asm("{ .reg .u64 t; cvta.to.shared.u64 t, %1; cvt.u32.u64 %0, t; }" : "=r"(a) : "l"(p));
    return a;
}
__device__ __forceinline__ void cp16(uint32_t dst, const void* src) {
    asm volatile("cp.async.cg.shared.global [%0], [%1], 16;" :: "r"(dst), "l"(src));
}
__device__ __forceinline__ void cp_commit() {
    asm volatile("cp.async.commit_group;" ::: "memory");
}
template <int N>
__device__ __forceinline__ void cp_wait() {
    asm volatile("cp.async.wait_group %0;" :: "n"(N) : "memory");
}
__device__ __forceinline__ void ldsm4(uint32_t* d, uint32_t addr) {
    asm volatile("ldmatrix.sync.aligned.m8n8.x4.shared.b16 {%0,%1,%2,%3}, [%4];"
        : "=r"(d[0]), "=r"(d[1]), "=r"(d[2]), "=r"(d[3]) : "r"(addr));
}
__device__ __forceinline__ void mma_bf16(float* d, const uint32_t* a,
                                         uint32_t b0, uint32_t b1) {
    asm volatile("mma.sync.aligned.m16n8k16.row.col.f32.bf16.bf16.f32 "
        "{%0,%1,%2,%3}, {%4,%5,%6,%7}, {%8,%9}, {%0,%1,%2,%3};"
        : "+f"(d[0]), "+f"(d[1]), "+f"(d[2]), "+f"(d[3])
        : "r"(a[0]), "r"(a[1]), "r"(a[2]), "r"(a[3]), "r"(b0), "r"(b1));
}

// ---------------------------------------------------------------------------
// Kernel 1: routing (stable argsort semantics)
// ---------------------------------------------------------------------------
__global__ void routing_kernel(const int* __restrict__ te)
{
    __shared__ int shist[512][NUM_E];
    const int tid = threadIdx.x;
    const int PER = NK / 512;
    const int start = tid * PER;

    #pragma unroll
    for (int i = 0; i < PER; i++) g_slot_token[start + i] = -1;

    int h[NUM_E];
    #pragma unroll
    for (int e = 0; e < NUM_E; e++) h[e] = 0;
    #pragma unroll 1
    for (int i = 0; i < PER; i++) h[te[start + i]]++;
    #pragma unroll
    for (int e = 0; e < NUM_E; e++) shist[tid][e] = h[e];
    __syncthreads();

    if (tid < NUM_E) {
        int acc = 0;
        #pragma unroll 1
        for (int t = 0; t < 512; t++) { int v = shist[t][tid]; shist[t][tid] = acc; acc += v; }
    }
    __syncthreads();

    int run[NUM_E];
    #pragma unroll
    for (int e = 0; e < NUM_E; e++) run[e] = shist[tid][e];
    #pragma unroll 1
    for (int i = 0; i < PER; i++) {
        int idx = start + i;
        int ex  = te[idx];
        int pos = run[ex]++;
        if (pos < CAP) {
            int slot = ex * CAP + pos;
            g_flat_slot[idx]   = slot;
            g_slot_token[slot] = idx >> 1;
        } else {
            g_flat_slot[idx] = -1;
        }
    }
}

// ---------------------------------------------------------------------------
// Kernel 2: gather x rows + split fp32 -> bf16 hi/lo
// ---------------------------------------------------------------------------
__global__ void gather_split_kernel(const float* __restrict__ x)
{
    const int slot = blockIdx.x;
    const int c    = threadIdx.x * 8;
    const int tok  = g_slot_token[slot];

    __nv_bfloat16 hi[8], lo[8];
    if (tok >= 0) {
        const float* src = x + (size_t)tok * HS + c;
        #pragma unroll
        for (int i = 0; i < 8; i++) {
            float v = src[i];
            __nv_bfloat16 h = __float2bfloat16(v);
            hi[i] = h;
            lo[i] = __float2bfloat16(v - __bfloat162float(h));
        }
    } else {
        #pragma unroll
        for (int i = 0; i < 8; i++) { hi[i] = __float2bfloat16(0.f); lo[i] = hi[i]; }
    }
    *(uint4*)&g_xg_hi[(size_t)slot * HS + c] = *(uint4*)hi;
    *(uint4*)&g_xg_lo[(size_t)slot * HS + c] = *(uint4*)lo;
}

// ---------------------------------------------------------------------------
// Kernel 3: transpose + split weights. src [E][K][N] fp32 -> dst [E][N][K] bf16
// ---------------------------------------------------------------------------
__global__ void wtrans_kernel(const float* __restrict__ w,
                              __nv_bfloat16* __restrict__ dhi,
                              __nv_bfloat16* __restrict__ dlo,
                              int K, int N)
{
    __shared__ float t[32][33];
    const int e     = blockIdx.z;
    const int nbase = blockIdx.x * 32;
    const int kbase = blockIdx.y * 32;
    const int tx = threadIdx.x, ty = threadIdx.y;

    const float* src = w + (size_t)e * K * N;
    #pragma unroll
    for (int i = 0; i < 4; i++) {
        int k = ty + i * 8;
        t[k][tx] = src[(size_t)(kbase + k) * N + nbase + tx];
    }
    __syncthreads();

    #pragma unroll
    for (int i = 0; i < 4; i++) {
        int n = ty + i * 8;
        float v = t[tx][n];
        __nv_bfloat16 h = __float2bfloat16(v);
        __nv_bfloat16 l = __float2bfloat16(v - __bfloat162float(h));
        size_t off = (size_t)e * N * K + (size_t)(nbase + n) * K + kbase + tx;
        dhi[off] = h;
        dlo[off] = l;
    }
}

// ---------------------------------------------------------------------------
// GeLU (tanh approximation, matches jax.nn.gelu default)
// ---------------------------------------------------------------------------
__device__ __forceinline__ float gelu_tanh(float x)
{
    float x3 = x * x * x;
    return 0.5f * x * (1.0f + tanhf(0.7978845608028654f * (x + 0.044715f * x3)));
}

// ---------------------------------------------------------------------------
// HMMA GEMM: 128x128x32 CTA tile, 8 warps (64x32 warp tile), 4-stage cp.async,
// 3-term bf16 split:  D = Ahi*Bhi + Ahi*Blo + Alo*Bhi  (fp32 accum).
// A: [E*CAP + m][K] pitch K;  B: [e*N + n][K] pitch K (both hi/lo).
// GELU=true:  C -> g_h_hi/g_h_lo (bf16 split, gelu applied), N = FFN
// GELU=false: C -> g_out (fp32), N = HS
// SMEM stage: {Ahi,Alo,Bhi,Blo} each 128 rows x 40 bf16 (pad 8) = 10240 B.
// ---------------------------------------------------------------------------
#define BKQ         32
#define ROWPITCH    40                      // bf16 elems per smem row (32 + 8 pad)
#define PART_BYTES  (128 * ROWPITCH * 2)    // 10240
#define STAGE_BYTES (4 * PART_BYTES)        // 40960
#define STAGES      4
#define SMEM_TOTAL  (STAGES * STAGE_BYTES)  // 163840

template <bool GELU>
__global__ __launch_bounds__(256, 1)
void moe_gemm_mma(int K, int N)
{
    extern __shared__ char smem[];
    const uint32_t sbase = smem_u32(smem);

    const __nv_bfloat16* __restrict__ Ahi = GELU ? g_xg_hi  : g_h_hi;
    const __nv_bfloat16* __restrict__ Alo = GELU ? g_xg_lo  : g_h_lo;
    const __nv_bfloat16* __restrict__ Bhi = GELU ? g_w1t_hi : g_w2t_hi;
    const __nv_bfloat16* __restrict__ Blo = GELU ? g_w1t_lo : g_w2t_lo;

    const int tid = threadIdx.x;
    const int wid = tid >> 5;
    const int lid = tid & 31;
    const int wm  = wid >> 2;        // 0..1 -> m offset wm*64
    const int wn  = wid & 3;         // 0..3 -> n offset wn*32

    const int e  = blockIdx.z;
    const int m0 = blockIdx.y * 128;
    const int n0 = blockIdx.x * 128;

    const size_t arow0 = (size_t)e * CAP + m0;
    const size_t brow0 = (size_t)e * N + n0;

    const int niter = K / BKQ;

    // ---- stage loader: 4 parts x 512 x 16B chunks, 2 per thread per part ----
    auto load_stage = [&](int s, int k0) {
        uint32_t sb = sbase + s * STAGE_BYTES;
        #pragma unroll
        for (int t = 0; t < 2; t++) {
            int j   = tid + t * 256;          // 0..511
            int row = j >> 2;                 // 0..127
            int c   = j & 3;                  // 16B chunk within 64B row
            uint32_t so = (uint32_t)(row * (ROWPITCH * 2) + c * 16);
            size_t ao = (arow0 + row) * K + k0 + c * 8;
            size_t bo = (brow0 + row) * K + k0 + c * 8;
            cp16(sb + 0 * PART_BYTES + so, Ahi + ao);
            cp16(sb + 1 * PART_BYTES + so, Alo + ao);
            cp16(sb + 2 * PART_BYTES + so, Bhi + bo);
            cp16(sb + 3 * PART_BYTES + so, Blo + bo);
        }
        cp_commit();
    };

    // prologue: stages 0..2
    load_stage(0, 0);
    load_stage(1, BKQ);
    load_stage(2, 2 * BKQ);

    float acc[4][4][4];
    #pragma unroll
    for (int i = 0; i < 4; i++)
        #pragma unroll
        for (int j = 0; j < 4; j++)
            #pragma unroll
            for (int q = 0; q < 4; q++) acc[i][j][q] = 0.0f;

    const int g = lid >> 3;     // ldmatrix group 0..3
    const int r = lid & 7;

    #pragma unroll 1
    for (int i = 0; i < niter; i++) {
        cp_wait<STAGES - 2>();
        __syncthreads();
        if (i + STAGES - 1 < niter) load_stage((i + STAGES - 1) & 3, (i + STAGES - 1) * BKQ);
        else                        cp_commit();   // keep drain invariant exact

        uint32_t sb = sbase + (i & 3) * STAGE_BYTES;

        #pragma unroll
        for (int ks = 0; ks < 2; ks++) {
            uint32_t ah[4][4], al[4][4], bh[2][4], bl[2][4];
            // A frags: groups map (m+8*(g&1), k+8*(g>>1))
            #pragma unroll
            for (int mf = 0; mf < 4; mf++) {
                uint32_t off = (uint32_t)(
                    (wm * 64 + mf * 16 + (g & 1) * 8 + r) * ROWPITCH
                    + ks * 16 + (g >> 1) * 8) * 2;
                ldsm4(ah[mf], sb + 0 * PART_BYTES + off);
                ldsm4(al[mf], sb + 1 * PART_BYTES + off);
            }
            // B frags: groups map (n+8*(g>>1), k+8*(g&1)); x4 = 2 n-frags
            #pragma unroll
            for (int p = 0; p < 2; p++) {
                uint32_t off = (uint32_t)(
                    (wn * 32 + p * 16 + (g >> 1) * 8 + r) * ROWPITCH
                    + ks * 16 + (g & 1) * 8) * 2;
                ldsm4(bh[p], sb + 2 * PART_BYTES + off);
                ldsm4(bl[p], sb + 3 * PART_BYTES + off);
            }
            #pragma unroll
            for (int mf = 0; mf < 4; mf++) {
                #pragma unroll
                for (int nf = 0; nf < 4; nf++) {
                    uint32_t bh0 = bh[nf >> 1][(nf & 1) * 2];
                    uint32_t bh1 = bh[nf >> 1][(nf & 1) * 2 + 1];
                    uint32_t bl0 = bl[nf >> 1][(nf & 1) * 2];
                    uint32_t bl1 = bl[nf >> 1][(nf & 1) * 2 + 1];
                    mma_bf16(acc[mf][nf], ah[mf], bh0, bh1);
                    mma_bf16(acc[mf][nf], ah[mf], bl0, bl1);
                    mma_bf16(acc[mf][nf], al[mf], bh0, bh1);
                }
            }
        }
        __syncthreads();
    }
    cp_wait<0>();
    __syncthreads();

    // ---- epilogue: stage accumulators through SMEM (reuse pipeline bufs) ----
    float (*sh)[132] = (float (*)[132])smem;
    #pragma unroll
    for (int mf = 0; mf < 4; mf++) {
        #pragma unroll
        for (int nf = 0; nf < 4; nf++) {
            int row = wm * 64 + mf * 16 + (lid >> 2);
            int col = wn * 32 + nf * 8 + (lid & 3) * 2;
            *(float2*)&sh[row][col]     = make_float2(acc[mf][nf][0], acc[mf][nf][1]);
            *(float2*)&sh[row + 8][col] = make_float2(acc[mf][nf][2], acc[mf][nf][3]);
        }
    }
    __syncthreads();

    if (GELU) {
        // 128 rows x 64 col-pairs, coalesced 4B stores of bf16x2
        #pragma unroll 1
        for (int t = 0; t < 32; t++) {
            int idx = tid + t * 256;
            int row = idx >> 6;
            int col = (idx & 63) * 2;
            float g0 = gelu_tanh(sh[row][col]);
            float g1 = gelu_tanh(sh[row][col + 1]);
            __nv_bfloat16 h0 = __float2bfloat16(g0);
            __nv_bfloat16 h1 = __float2bfloat16(g1);
            __nv_bfloat16 l0 = __float2bfloat16(g0 - __bfloat162float(h0));
            __nv_bfloat16 l1 = __float2bfloat16(g1 - __bfloat162float(h1));
            size_t off = (arow0 + row) * N + n0 + col;
            __nv_bfloat162 vh; vh.x = h0; vh.y = h1;
            __nv_bfloat162 vl; vl.x = l0; vl.y = l1;
            *(__nv_bfloat162*)&g_h_hi[off] = vh;
            *(__nv_bfloat162*)&g_h_lo[off] = vl;
        }
    } else {
        // 128 rows x 32 float4, coalesced
        #pragma unroll 1
        for (int t = 0; t < 16; t++) {
            int idx = tid + t * 256;
            int row = idx >> 5;
            int col = (idx & 31) * 4;
            float4 v = *(float4*)&sh[row][col];
            *(float4*)&g_out[(arow0 + row) * N + n0 + col] = v;
        }
    }
}

// ---------------------------------------------------------------------------
// Kernel: combine
// ---------------------------------------------------------------------------
__global__ void combine_kernel(const float* __restrict__ ew,
                               const float* __restrict__ bias,
                               float* __restrict__ y)
{
    const int t = blockIdx.x;
    const int c = threadIdx.x * 4;

    float4 acc = *(const float4*)&bias[c];
    #pragma unroll
    for (int k = 0; k < TOPK; k++) {
        int slot = g_flat_slot[t * TOPK + k];
        if (slot >= 0) {
            float  w = ew[t * TOPK + k];
            float4 v = *(const float4*)&g_out[(size_t)slot * HS + c];
            acc.x += v.x * w; acc.y += v.y * w;
            acc.z += v.z * w; acc.w += v.w * w;
        }
    }
    *(float4*)&y[(size_t)t * HS + c] = acc;
}

// ---------------------------------------------------------------------------
// Entry point
// ---------------------------------------------------------------------------
extern "C" void kernel_launch(void* const* d_in, const int* in_sizes, int n_in,
                              void* d_out, int out_size)
{
    const float* x    = (const float*)d_in[0];
    const float* ew   = (const float*)d_in[1];
    const float* w1   = (const float*)d_in[2];
    const float* w2   = (const float*)d_in[3];
    const float* bias = (const float*)d_in[4];
    const int*   te   = (const int*)d_in[5];
    float*       y    = (float*)d_out;

    cudaFuncSetAttribute(moe_gemm_mma<true>,
                         cudaFuncAttributeMaxDynamicSharedMemorySize, SMEM_TOTAL);
    cudaFuncSetAttribute(moe_gemm_mma<false>,
                         cudaFuncAttributeMaxDynamicSharedMemorySize, SMEM_TOTAL);

    // 1) routing
    routing_kernel<<<1, 512>>>(te);

    // 2) gather + split x
    gather_split_kernel<<<NUM_E * CAP, 128>>>(x);

    // 3) weight transpose + split
    {
        dim3 b(32, 8);
        __nv_bfloat16 *w1t_hi, *w1t_lo, *w2t_hi, *w2t_lo;
        cudaGetSymbolAddress((void**)&w1t_hi, g_w1t_hi);
        cudaGetSymbolAddress((void**)&w1t_lo, g_w1t_lo);
        cudaGetSymbolAddress((void**)&w2t_hi, g_w2t_hi);
        cudaGetSymbolAddress((void**)&w2t_lo, g_w2t_lo);
        dim3 g1(FFN / 32, HS / 32, NUM_E);
        wtrans_kernel<<<g1, b>>>(w1, w1t_hi, w1t_lo, HS, FFN);
        dim3 g2(HS / 32, FFN / 32, NUM_E);
        wtrans_kernel<<<g2, b>>>(w2, w2t_hi, w2t_lo, FFN, HS);
    }

    // 4) GEMM1 + GeLU: [E,CAP,HS] @ [E,HS,FFN]^T-layout -> g_h (bf16 hi/lo)
    {
        dim3 grid(FFN / 128, CAP / 128, NUM_E);
        moe_gemm_mma<true><<<grid, 256, SMEM_TOTAL>>>(HS, FFN);
    }

    // 5) GEMM2: [E,CAP,FFN] @ [E,FFN,HS]^T-layout -> g_out (fp32)
    {
        dim3 grid(HS / 128, CAP / 128, NUM_E);
        moe_gemm_mma<false><<<grid, 256, SMEM_TOTAL>>>(FFN, HS);
    }

    // 6) combine
    combine_kernel<<<T_TOK, 256>>>(ew, bias, y);
}

// round 7
// speedup vs baseline: 5.2933x; 2.5567x over previous
#include <cuda_runtime.h>
#include <cuda_fp16.h>
#include <math.h>
#include <stdint.h>

// ---------------------------------------------------------------------------
// Problem constants
// ---------------------------------------------------------------------------
#define NUM_E   8
#define TOPK    2
#define T_TOK   8192
#define NK      (T_TOK * TOPK)
#define HS      1024
#define FFN     4096
#define CAP     2048

// ---------------------------------------------------------------------------
// Device scratch
// ---------------------------------------------------------------------------
__device__ int    g_flat_slot[NK];
__device__ int    g_slot_token[NUM_E * CAP];
__device__ __half g_xg[(size_t)NUM_E * CAP * HS];       // gathered x, fp16
__device__ __half g_w1t[(size_t)NUM_E * FFN * HS];      // w1^T [E][FFN][HS] fp16
__device__ __half g_w2t[(size_t)NUM_E * HS * FFN];      // w2^T [E][HS][FFN] fp16
__device__ __half g_h[(size_t)NUM_E * CAP * FFN];       // gelu(h) fp16
__device__ float  g_out[(size_t)NUM_E * CAP * HS];      // expert outputs fp32

// ---------------------------------------------------------------------------
// PTX helpers (baseline PTX only — valid at compute_103 target)
// ---------------------------------------------------------------------------
__device__ __forceinline__ uint32_t smem_u32(const void* p) {
    uint32_t a;
    asm("{ .reg .u64 t; cvta.to.shared.u64 t, %1; cvt.u32.u64 %0, t; }" : "=r"(a) : "l"(p));
    return a;
}
__device__ __forceinline__ void cp16(uint32_t dst, const void* src) {
    asm volatile("cp.async.cg.shared.global [%0], [%1], 16;" :: "r"(dst), "l"(src));
}
__device__ __forceinline__ void cp_commit() {
    asm volatile("cp.async.commit_group;" ::: "memory");
}
template <int N>
__device__ __forceinline__ void cp_wait() {
    asm volatile("cp.async.wait_group %0;" :: "n"(N) : "memory");
}
__device__ __forceinline__ void ldsm4(uint32_t* d, uint32_t addr) {
    asm volatile("ldmatrix.sync.aligned.m8n8.x4.shared.b16 {%0,%1,%2,%3}, [%4];"
        : "=r"(d[0]), "=r"(d[1]), "=r"(d[2]), "=r"(d[3]) : "r"(addr));
}
__device__ __forceinline__ void mma_f16(float* d, const uint32_t* a,
                                        uint32_t b0, uint32_t b1) {
    asm volatile("mma.sync.aligned.m16n8k16.row.col.f32.f16.f16.f32 "
        "{%0,%1,%2,%3}, {%4,%5,%6,%7}, {%8,%9}, {%0,%1,%2,%3};"
        : "+f"(d[0]), "+f"(d[1]), "+f"(d[2]), "+f"(d[3])
        : "r"(a[0]), "r"(a[1]), "r"(a[2]), "r"(a[3]), "r"(b0), "r"(b1));
}

// ---------------------------------------------------------------------------
// Kernel 1: routing (stable argsort semantics)
// ---------------------------------------------------------------------------
__global__ void routing_kernel(const int* __restrict__ te)
{
    __shared__ int shist[512][NUM_E];
    const int tid = threadIdx.x;
    const int PER = NK / 512;
    const int start = tid * PER;

    #pragma unroll
    for (int i = 0; i < PER; i++) g_slot_token[start + i] = -1;

    int h[NUM_E];
    #pragma unroll
    for (int e = 0; e < NUM_E; e++) h[e] = 0;
    #pragma unroll 1
    for (int i = 0; i < PER; i++) h[te[start + i]]++;
    #pragma unroll
    for (int e = 0; e < NUM_E; e++) shist[tid][e] = h[e];
    __syncthreads();

    if (tid < NUM_E) {
        int acc = 0;
        #pragma unroll 1
        for (int t = 0; t < 512; t++) { int v = shist[t][tid]; shist[t][tid] = acc; acc += v; }
    }
    __syncthreads();

    int run[NUM_E];
    #pragma unroll
    for (int e = 0; e < NUM_E; e++) run[e] = shist[tid][e];
    #pragma unroll 1
    for (int i = 0; i < PER; i++) {
        int idx = start + i;
        int ex  = te[idx];
        int pos = run[ex]++;
        if (pos < CAP) {
            int slot = ex * CAP + pos;
            g_flat_slot[idx]   = slot;
            g_slot_token[slot] = idx >> 1;
        } else {
            g_flat_slot[idx] = -1;
        }
    }
}

// ---------------------------------------------------------------------------
// Kernel 2: gather x rows, convert fp32 -> fp16
// ---------------------------------------------------------------------------
__global__ void gather_kernel(const float* __restrict__ x)
{
    const int slot = blockIdx.x;
    const int c    = threadIdx.x * 8;
    const int tok  = g_slot_token[slot];

    __half v[8];
    if (tok >= 0) {
        const float* src = x + (size_t)tok * HS + c;
        #pragma unroll
        for (int i = 0; i < 8; i++) v[i] = __float2half_rn(src[i]);
    } else {
        #pragma unroll
        for (int i = 0; i < 8; i++) v[i] = __float2half_rn(0.f);
    }
    *(uint4*)&g_xg[(size_t)slot * HS + c] = *(uint4*)v;
}

// ---------------------------------------------------------------------------
// Kernel 3: transpose + convert weights. src [E][K][N] fp32 -> dst [E][N][K] fp16
// ---------------------------------------------------------------------------
__global__ void wtrans_kernel(const float* __restrict__ w,
                              __half* __restrict__ dst,
                              int K, int N)
{
    __shared__ float t[32][33];
    const int e     = blockIdx.z;
    const int nbase = blockIdx.x * 32;
    const int kbase = blockIdx.y * 32;
    const int tx = threadIdx.x, ty = threadIdx.y;

    const float* src = w + (size_t)e * K * N;
    #pragma unroll
    for (int i = 0; i < 4; i++) {
        int k = ty + i * 8;
        t[k][tx] = src[(size_t)(kbase + k) * N + nbase + tx];
    }
    __syncthreads();

    #pragma unroll
    for (int i = 0; i < 4; i++) {
        int n = ty + i * 8;
        size_t off = (size_t)e * N * K + (size_t)(nbase + n) * K + kbase + tx;
        dst[off] = __float2half_rn(t[tx][n]);
    }
}

// ---------------------------------------------------------------------------
// GeLU (tanh approximation, matches jax.nn.gelu default)
// ---------------------------------------------------------------------------
__device__ __forceinline__ float gelu_tanh(float x)
{
    float x3 = x * x * x;
    return 0.5f * x * (1.0f + tanhf(0.7978845608028654f * (x + 0.044715f * x3)));
}

// ---------------------------------------------------------------------------
// HMMA GEMM: 128x128x32 CTA tile, 8 warps (64x32 warp tile), 4-stage cp.async.
// Pure fp16 operands, fp32 accumulation, 1 MMA per fragment pair.
// A: [E*CAP + m][K] pitch K;  B: [e*N + n][K] pitch K (fp16).
// GELU=true:  C -> g_h (fp16, gelu applied), N = FFN
// GELU=false: C -> g_out (fp32), N = HS
// SMEM stage: {A, B} each 128 rows x 40 fp16 (32 + 8 pad) = 10240 B -> 20 KB.
// 4 stages = 80 KB -> 2 CTAs/SM.
// ---------------------------------------------------------------------------
#define BKQ         32
#define ROWPITCH    40                      // fp16 elems per smem row (32 + 8 pad)
#define PART_BYTES  (128 * ROWPITCH * 2)    // 10240
#define STAGE_BYTES (2 * PART_BYTES)        // 20480
#define STAGES      4
#define SMEM_TOTAL  (STAGES * STAGE_BYTES)  // 81920

template <bool GELU>
__global__ __launch_bounds__(256, 2)
void moe_gemm_mma(int K, int N)
{
    extern __shared__ char smem[];
    const uint32_t sbase = smem_u32(smem);

    const __half* __restrict__ A = GELU ? g_xg  : g_h;
    const __half* __restrict__ B = GELU ? g_w1t : g_w2t;

    const int tid = threadIdx.x;
    const int wid = tid >> 5;
    const int lid = tid & 31;
    const int wm  = wid >> 2;        // 0..1 -> m offset wm*64
    const int wn  = wid & 3;         // 0..3 -> n offset wn*32

    const int e  = blockIdx.z;
    const int m0 = blockIdx.y * 128;
    const int n0 = blockIdx.x * 128;

    const size_t arow0 = (size_t)e * CAP + m0;
    const size_t brow0 = (size_t)e * N + n0;

    const int niter = K / BKQ;

    // ---- stage loader: 2 parts x 512 x 16B chunks, 2 per thread per part ----
    auto load_stage = [&](int s, int k0) {
        uint32_t sb = sbase + s * STAGE_BYTES;
        #pragma unroll
        for (int t = 0; t < 2; t++) {
            int j   = tid + t * 256;          // 0..511
            int row = j >> 2;                 // 0..127
            int c   = j & 3;                  // 16B chunk within 64B row
            uint32_t so = (uint32_t)(row * (ROWPITCH * 2) + c * 16);
            cp16(sb + 0 * PART_BYTES + so, A + (arow0 + row) * K + k0 + c * 8);
            cp16(sb + 1 * PART_BYTES + so, B + (brow0 + row) * K + k0 + c * 8);
        }
        cp_commit();
    };

    load_stage(0, 0);
    load_stage(1, BKQ);
    load_stage(2, 2 * BKQ);

    float acc[4][4][4];
    #pragma unroll
    for (int i = 0; i < 4; i++)
        #pragma unroll
        for (int j = 0; j < 4; j++)
            #pragma unroll
            for (int q = 0; q < 4; q++) acc[i][j][q] = 0.0f;

    const int g = lid >> 3;     // ldmatrix group 0..3
    const int r = lid & 7;

    #pragma unroll 1
    for (int i = 0; i < niter; i++) {
        cp_wait<STAGES - 2>();
        __syncthreads();
        if (i + STAGES - 1 < niter) load_stage((i + STAGES - 1) & 3, (i + STAGES - 1) * BKQ);
        else                        cp_commit();   // keep drain invariant exact

        uint32_t sb = sbase + (i & 3) * STAGE_BYTES;

        #pragma unroll
        for (int ks = 0; ks < 2; ks++) {
            uint32_t ah[4][4], bh[2][4];
            // A frags: groups map (m + 8*(g&1), k + 8*(g>>1))
            #pragma unroll
            for (int mf = 0; mf < 4; mf++) {
                uint32_t off = (uint32_t)(
                    (wm * 64 + mf * 16 + (g & 1) * 8 + r) * ROWPITCH
                    + ks * 16 + (g >> 1) * 8) * 2;
                ldsm4(ah[mf], sb + 0 * PART_BYTES + off);
            }
            // B frags: groups map (n + 8*(g>>1), k + 8*(g&1)); x4 = 2 n-frags
            #pragma unroll
            for (int p = 0; p < 2; p++) {
                uint32_t off = (uint32_t)(
                    (wn * 32 + p * 16 + (g >> 1) * 8 + r) * ROWPITCH
                    + ks * 16 + (g & 1) * 8) * 2;
                ldsm4(bh[p], sb + 1 * PART_BYTES + off);
            }
            #pragma unroll
            for (int mf = 0; mf < 4; mf++) {
                #pragma unroll
                for (int nf = 0; nf < 4; nf++) {
                    mma_f16(acc[mf][nf], ah[mf],
                            bh[nf >> 1][(nf & 1) * 2],
                            bh[nf >> 1][(nf & 1) * 2 + 1]);
                }
            }
        }
        __syncthreads();
    }
    cp_wait<0>();
    __syncthreads();

    // ---- epilogue: stage accumulators through SMEM (reuse pipeline bufs) ----
    // float[128][132] = 67584 B <= 81920 B
    float (*sh)[132] = (float (*)[132])smem;
    #pragma unroll
    for (int mf = 0; mf < 4; mf++) {
        #pragma unroll
        for (int nf = 0; nf < 4; nf++) {
            int row = wm * 64 + mf * 16 + (lid >> 2);
            int col = wn * 32 + nf * 8 + (lid & 3) * 2;
            *(float2*)&sh[row][col]     = make_float2(acc[mf][nf][0], acc[mf][nf][1]);
            *(float2*)&sh[row + 8][col] = make_float2(acc[mf][nf][2], acc[mf][nf][3]);
        }
    }
    __syncthreads();

    if (GELU) {
        // 128 rows x 64 col-pairs -> fp16x2 stores (coalesced 4B)
        #pragma unroll 1
        for (int t = 0; t < 32; t++) {
            int idx = tid + t * 256;
            int row = idx >> 6;
            int col = (idx & 63) * 2;
            __half2 v;
            v.x = __float2half_rn(gelu_tanh(sh[row][col]));
            v.y = __float2half_rn(gelu_tanh(sh[row][col + 1]));
            *(__half2*)&g_h[(arow0 + row) * N + n0 + col] = v;
        }
    } else {
        // 128 rows x 32 float4, coalesced
        #pragma unroll 1
        for (int t = 0; t < 16; t++) {
            int idx = tid + t * 256;
            int row = idx >> 5;
            int col = (idx & 31) * 4;
            float4 v = *(float4*)&sh[row][col];
            *(float4*)&g_out[(arow0 + row) * N + n0 + col] = v;
        }
    }
}

// ---------------------------------------------------------------------------
// Kernel: combine
// ---------------------------------------------------------------------------
__global__ void combine_kernel(const float* __restrict__ ew,
                               const float* __restrict__ bias,
                               float* __restrict__ y)
{
    const int t = blockIdx.x;
    const int c = threadIdx.x * 4;

    float4 acc = *(const float4*)&bias[c];
    #pragma unroll
    for (int k = 0; k < TOPK; k++) {
        int slot = g_flat_slot[t * TOPK + k];
        if (slot >= 0) {
            float  w = ew[t * TOPK + k];
            float4 v = *(const float4*)&g_out[(size_t)slot * HS + c];
            acc.x += v.x * w; acc.y += v.y * w;
            acc.z += v.z * w; acc.w += v.w * w;
        }
    }
    *(float4*)&y[(size_t)t * HS + c] = acc;
}

// ---------------------------------------------------------------------------
// Entry point
// ---------------------------------------------------------------------------
extern "C" void kernel_launch(void* const* d_in, const int* in_sizes, int n_in,
                              void* d_out, int out_size)
{
    const float* x    = (const float*)d_in[0];
    const float* ew   = (const float*)d_in[1];
    const float* w1   = (const float*)d_in[2];
    const float* w2   = (const float*)d_in[3];
    const float* bias = (const float*)d_in[4];
    const int*   te   = (const int*)d_in[5];
    float*       y    = (float*)d_out;

    cudaFuncSetAttribute(moe_gemm_mma<true>,
                         cudaFuncAttributeMaxDynamicSharedMemorySize, SMEM_TOTAL);
    cudaFuncSetAttribute(moe_gemm_mma<false>,
                         cudaFuncAttributeMaxDynamicSharedMemorySize, SMEM_TOTAL);

    // 1) routing
    routing_kernel<<<1, 512>>>(te);

    // 2) gather + fp16 convert
    gather_kernel<<<NUM_E * CAP, 128>>>(x);

    // 3) weight transpose + fp16 convert
    {
        dim3 b(32, 8);
        __half *w1t, *w2t;
        cudaGetSymbolAddress((void**)&w1t, g_w1t);
        cudaGetSymbolAddress((void**)&w2t, g_w2t);
        dim3 g1(FFN / 32, HS / 32, NUM_E);
        wtrans_kernel<<<g1, b>>>(w1, w1t, HS, FFN);
        dim3 g2(HS / 32, FFN / 32, NUM_E);
        wtrans_kernel<<<g2, b>>>(w2, w2t, FFN, HS);
    }

    // 4) GEMM1 + GeLU: [E,CAP,HS] @ w1^T-layout -> g_h (fp16)
    {
        dim3 grid(FFN / 128, CAP / 128, NUM_E);
        moe_gemm_mma<true><<<grid, 256, SMEM_TOTAL>>>(HS, FFN);
    }

    // 5) GEMM2: [E,CAP,FFN] @ w2^T-layout -> g_out (fp32)
    {
        dim3 grid(HS / 128, CAP / 128, NUM_E);
        moe_gemm_mma<false><<<grid, 256, SMEM_TOTAL>>>(FFN, HS);
    }

    // 6) combine
    combine_kernel<<<T_TOK, 256>>>(ew, bias, y);
}